// round 2
// baseline (speedup 1.0000x reference)
#include <cuda_runtime.h>
#include <cstdint>

// PANNAcceptor: out[b] = lin_w @ (W[x_{L-1}] ... W[x_0] @ e0) + lin_b
// Round 2: 2-CTA cluster per batch, row-split mat-vec, DSMEM h-exchange.
// Each CTA streams 128 KB/step (half the matrix) -> halves the per-SM
// L1-wavefront floor that bounds the straggler batch; one cluster.sync/step.

#define NST 256
#define THREADS 256          // 8 warps
#define ROWS_PER_CTA 128
#define ROWS_PER_WARP 16     // 8 warps * 16 rows = 128

__device__ __forceinline__ uint32_t smem_u32(const void* p) {
    uint32_t a;
    asm("{ .reg .u64 t; cvta.to.shared.u64 t, %1; cvt.u32.u64 %0, t; }" : "=r"(a) : "l"(p));
    return a;
}

__device__ __forceinline__ void st_shared_remote(uint32_t local_addr, uint32_t peer_rank, float v) {
    uint32_t rem;
    asm volatile("mapa.shared::cluster.u32 %0, %1, %2;" : "=r"(rem) : "r"(local_addr), "r"(peer_rank));
    asm volatile("st.shared::cluster.f32 [%0], %1;" :: "r"(rem), "f"(v) : "memory");
}

__global__ __launch_bounds__(THREADS)
__cluster_dims__(2, 1, 1)
void pann_cluster_kernel(const int* __restrict__ xs,
                         const int* __restrict__ lengths,
                         const float* __restrict__ W,
                         const float* __restrict__ lin_w,
                         const float* __restrict__ lin_b,
                         float* __restrict__ out,
                         int S)
{
    __shared__ float hbuf[2][NST];

    const int b    = blockIdx.x >> 1;         // batch = cluster id
    const int tid  = threadIdx.x;
    const int warp = tid >> 5;
    const int lane = tid & 31;

    uint32_t rank;
    asm("mov.u32 %0, %%cluster_ctarank;" : "=r"(rank));
    const uint32_t peer = rank ^ 1u;
    const uint32_t hbase = smem_u32(hbuf);

    // h0 = one-hot(state 0): each CTA initializes its OWN full copy.
    hbuf[0][tid] = (tid == 0) ? 1.0f : 0.0f;
    __syncthreads();

    const int L = lengths[b];
    const int* xrow = xs + (size_t)b * S;

    int cur = 0;
    const int i0 = (int)rank * ROWS_PER_CTA + warp * ROWS_PER_WARP;  // this warp's rows

    for (int t = 0; t < L; ++t) {
        const int a = __ldg(xrow + t);
        const float* Wa = W + (size_t)a * (NST * NST);
        const float* hsrc = hbuf[cur];
        const int nxt = cur ^ 1;
        float* hdst = hbuf[nxt];
        const uint32_t hdst_u32 = hbase + (uint32_t)nxt * (NST * 4);

        // Lane's column slice of h: cols [4l,4l+4) and [128+4l, 128+4l+4)
        const float4 hA = *(const float4*)(hsrc + lane * 4);
        const float4 hB = *(const float4*)(hsrc + 128 + lane * 4);

        #pragma unroll 4
        for (int r = 0; r < ROWS_PER_WARP; ++r) {
            const int i = i0 + r;
            const float4* p = (const float4*)(Wa + (size_t)i * NST + lane * 4);
            const float4 wA = p[0];    // contiguous 512 B per warp-load
            const float4 wB = p[32];

            float s = wA.x * hA.x + wA.y * hA.y + wA.z * hA.z + wA.w * hA.w
                    + wB.x * hB.x + wB.y * hB.y + wB.z * hB.z + wB.w * hB.w;

            s += __shfl_xor_sync(0xffffffffu, s, 16);
            s += __shfl_xor_sync(0xffffffffu, s, 8);
            s += __shfl_xor_sync(0xffffffffu, s, 4);
            s += __shfl_xor_sync(0xffffffffu, s, 2);
            s += __shfl_xor_sync(0xffffffffu, s, 1);
            if (lane == 0) {
                hdst[i] = s;                                    // my copy
                st_shared_remote(hdst_u32 + (uint32_t)i * 4, peer, s);  // peer's copy
            }
        }

        // One cluster barrier per step:
        //  - arrive (release) orders my local + remote h stores
        //  - wait (acquire) makes peer's stores visible before next step's reads
        // Reads of hbuf[cur] happened BEFORE this barrier; writes to hbuf[nxt]
        // by the peer happen AFTER its previous barrier -> no buffer race.
        asm volatile("barrier.cluster.arrive.aligned;" ::: "memory");
        asm volatile("barrier.cluster.wait.aligned;" ::: "memory");

        cur = nxt;
    }

    // Linear head: rank 0 holds a full copy of h_final.
    if (rank == 0 && warp < 2) {
        const float* hf = hbuf[cur];
        const int k = warp;
        float s = 0.0f;
        #pragma unroll
        for (int i = lane; i < NST; i += 32)
            s += lin_w[k * NST + i] * hf[i];
        s += __shfl_xor_sync(0xffffffffu, s, 16);
        s += __shfl_xor_sync(0xffffffffu, s, 8);
        s += __shfl_xor_sync(0xffffffffu, s, 4);
        s += __shfl_xor_sync(0xffffffffu, s, 2);
        s += __shfl_xor_sync(0xffffffffu, s, 1);
        if (lane == 0) out[b * 2 + k] = s + lin_b[k];
    }
}

extern "C" void kernel_launch(void* const* d_in, const int* in_sizes, int n_in,
                              void* d_out, int out_size)
{
    const int*   xs      = (const int*)d_in[0];
    const int*   lengths = (const int*)d_in[1];
    const float* W       = (const float*)d_in[2];
    const float* lin_w   = (const float*)d_in[3];
    const float* lin_b   = (const float*)d_in[4];
    float*       out     = (float*)d_out;

    const int B = in_sizes[1];
    const int S = in_sizes[0] / B;

    pann_cluster_kernel<<<2 * B, THREADS>>>(xs, lengths, W, lin_w, lin_b, out, S);
}